// round 15
// baseline (speedup 1.0000x reference)
#include <cuda_runtime.h>
#include <cuda_bf16.h>

#define NB     65536
#define TPB    128                    // 4 warps
#define WPB    4
#define NP     8                      // pairs per warp (pair = 2 batches)
#define NBLK   (NB / (WPB * 2 * NP))  // 1024 blocks
#define PAIRF4     150                // one array's pair slice: 150 float4
#define PAIR_BYTES 2400
#define STAGE_BYTES (2 * PAIR_BYTES)  // A + Y
#define WARP_SMEM  (2 * STAGE_BYTES)  // double buffer = 9600
#define SMEM_BYTES (WPB * WARP_SMEM)  // 38400 -> 5 blocks/SM (20 warps)

#define LN2      0.69314718055994530942f
#define CLAMP_L2 (-144.26950408889634f)   // -100 / ln2

typedef unsigned long long ull;
#define F32X2_NEG1 0xBF800000BF800000ULL
#define F32X2_ONE  0x3F8000003F800000ULL

union F2U { float2 f; ull u; };

#define FMA2(d, a, b, c) asm("fma.rn.f32x2 %0, %1, %2, %3;" : "=l"(d) : "l"(a), "l"(b), "l"(c))
#define ADD2(d, a, b)    asm("add.rn.f32x2 %0, %1, %2;"     : "=l"(d) : "l"(a), "l"(b))

__device__ float        g_partials[NBLK];
__device__ unsigned int g_counter = 0;

__device__ __forceinline__ float clog2_(float x) {           // clip(log p,-100)/ln2
    return fmaxf(__log2f(x), CLAMP_L2);
}
__device__ __forceinline__ float bce1(float p, float y) {
    float lp = fmaxf(__logf(p), -100.0f);
    float lm = fmaxf(__logf(1.0f - p), -100.0f);
    return -(y * lp + (1.0f - y) * lm);
}

__device__ __forceinline__ void cp16(void* dst_smem, const void* src_gmem) {
    unsigned s = (unsigned)__cvta_generic_to_shared(dst_smem);
    asm volatile("cp.async.cg.shared.global [%0], [%1], 16;" :: "r"(s), "l"(src_gmem) : "memory");
}

// Warp-scope stage of one pair: 150 float4 from A and 150 from Y (contiguous).
__device__ __forceinline__ void stage_pair(char* dst, const float4* gA, const float4* gY, int lane)
{
    #pragma unroll
    for (int i = 0; i < 5; ++i) {
        int idx = i * 32 + lane;
        if (idx < PAIRF4) {
            cp16(dst + idx * 16,              gA + idx);
            cp16(dst + PAIR_BYTES + idx * 16, gY + idx);
        }
    }
}

// One float4 chunk, packed-pair arithmetic (FFMA2). acc/slog in lg2 domain.
__device__ __forceinline__ void chunk_accum(const float4 av[3], const float4 yv[3],
                                            ull accp[3][3], ull slogp[3])
{
    ull yp[3][2];
    #pragma unroll
    for (int t = 0; t < 3; ++t) {
        F2U y0; y0.f = make_float2(yv[t].x, yv[t].y);
        F2U y1; y1.f = make_float2(yv[t].z, yv[t].w);
        yp[t][0] = y0.u; yp[t][1] = y1.u;
    }
    #pragma unroll
    for (int s = 0; s < 3; ++s) {
        F2U a0; a0.f = make_float2(av[s].x, av[s].y);
        F2U a1; a1.f = make_float2(av[s].z, av[s].w);
        ull om0, om1;                      // (1 - p) packed
        FMA2(om0, a0.u, F32X2_NEG1, F32X2_ONE);
        FMA2(om1, a1.u, F32X2_NEG1, F32X2_ONE);
        F2U o0; o0.u = om0;
        F2U o1; o1.u = om1;
        F2U lm0; lm0.f = make_float2(__log2f(o0.f.x), __log2f(o0.f.y));
        F2U lm1; lm1.f = make_float2(__log2f(o1.f.x), __log2f(o1.f.y));
        F2U lp0; lp0.f = make_float2(clog2_(av[s].x), clog2_(av[s].y));
        F2U lp1; lp1.f = make_float2(clog2_(av[s].z), clog2_(av[s].w));
        ull df0, df1;                      // lp - lm
        FMA2(df0, lm0.u, F32X2_NEG1, lp0.u);
        FMA2(df1, lm1.u, F32X2_NEG1, lp1.u);
        ADD2(slogp[s], slogp[s], lm0.u);
        ADD2(slogp[s], slogp[s], lm1.u);
        #pragma unroll
        for (int t = 0; t < 3; ++t) {
            FMA2(accp[s][t], yp[t][0], df0, accp[s][t]);
            FMA2(accp[s][t], yp[t][1], df1, accp[s][t]);
        }
    }
}

extern __shared__ char smem[];

__global__ void __launch_bounds__(TPB)
loss_kernel(const float* __restrict__ A, const float* __restrict__ CAT,
            const float* __restrict__ Y, const float* __restrict__ CATL,
            float* __restrict__ out)
{
    const int tid  = threadIdx.x;
    const int w    = tid >> 5;
    const int lane = tid & 31;
    const int h    = lane >> 4;          // batch within pair (0,1)
    const int r    = lane & 15;          // lane within 16-lane batch group

    char* buf[2] = { smem + w * WARP_SMEM, smem + w * WARP_SMEM + STAGE_BYTES };

    const size_t p0 = ((size_t)blockIdx.x * WPB + w) * NP;   // first pair id
    const float4* gA = reinterpret_cast<const float4*>(A);
    const float4* gY = reinterpret_cast<const float4*>(Y);

    // Prologue: stage pairs p0, p0+1.
    stage_pair(buf[0], gA + p0 * PAIRF4, gY + p0 * PAIRF4, lane);
    asm volatile("cp.async.commit_group;" ::: "memory");
    stage_pair(buf[1], gA + (p0 + 1) * PAIRF4, gY + (p0 + 1) * PAIRF4, lane);
    asm volatile("cp.async.commit_group;" ::: "memory");

    float vsum = 0.0f;

    #pragma unroll 2
    for (int p = 0; p < NP; ++p) {
        asm volatile("cp.async.wait_group 1;" ::: "memory");
        __syncwarp();

        const int  b   = (int)(p0 + p) * 2 + h;              // this lane's batch
        const char* aq = buf[p & 1] + h * 1200;              // rows at s*400
        const char* yq = buf[p & 1] + PAIR_BYTES + h * 1200;

        // Prefetch epilogue operands (hidden under the log chains below).
        float c0 = 0.5f, c1 = 0.5f, c2 = 0.5f, l0 = 0.5f, l1 = 0.5f, l2 = 0.5f;
        if (r == 0) {
            c0 = CAT[3 * b + 0];  c1 = CAT[3 * b + 1];  c2 = CAT[3 * b + 2];
            l0 = CATL[3 * b + 0]; l1 = CATL[3 * b + 1]; l2 = CATL[3 * b + 2];
        }

        ull accp[3][3] = {};
        ull slogp[3]   = {};

        // Chunk c = r (all 16 lanes).
        {
            float4 av[3], yv[3];
            #pragma unroll
            for (int s = 0; s < 3; ++s) {
                av[s] = *reinterpret_cast<const float4*>(aq + s * 400 + r * 16);
                yv[s] = *reinterpret_cast<const float4*>(yq + s * 400 + r * 16);
            }
            chunk_accum(av, yv, accp, slogp);
        }
        // Chunk c = 16 + r (lanes r<8 only).
        if (r < 8) {
            float4 av[3], yv[3];
            #pragma unroll
            for (int s = 0; s < 3; ++s) {
                av[s] = *reinterpret_cast<const float4*>(aq + s * 400 + (16 + r) * 16);
                yv[s] = *reinterpret_cast<const float4*>(yq + s * 400 + (16 + r) * 16);
            }
            chunk_accum(av, yv, accp, slogp);
        }

        float acc[3][3], slog[3];
        #pragma unroll
        for (int s = 0; s < 3; ++s) {
            F2U t0; t0.u = slogp[s];
            slog[s] = t0.f.x + t0.f.y;
            #pragma unroll
            for (int t = 0; t < 3; ++t) {
                F2U t1; t1.u = accp[s][t];
                acc[s][t] = t1.f.x + t1.f.y;
            }
        }

        // Ragged elements 96..99: lanes r=8..11 take element 96+(r&3).
        {
            const int e = 96 + (r & 3);       // safe address for all lanes
            float ra[3], ry[3], dfr[3], lmr[3];
            #pragma unroll
            for (int s = 0; s < 3; ++s) {
                ra[s] = *reinterpret_cast<const float*>(aq + s * 400 + e * 4);
                ry[s] = *reinterpret_cast<const float*>(yq + s * 400 + e * 4);
                float lp = clog2_(ra[s]);
                lmr[s]   = __log2f(1.0f - ra[s]);
                dfr[s]   = lp - lmr[s];
            }
            if ((r >> 2) == 2) {              // r in [8,12)
                #pragma unroll
                for (int s = 0; s < 3; ++s) {
                    slog[s] += lmr[s];
                    #pragma unroll
                    for (int t = 0; t < 3; ++t)
                        acc[s][t] = fmaf(ry[t], dfr[s], acc[s][t]);
                }
            }
        }

        // Done reading this buffer; refill it with pair p+2.
        __syncwarp();
        if (p + 2 < NP)
            stage_pair(buf[p & 1], gA + (p0 + p + 2) * PAIRF4, gY + (p0 + p + 2) * PAIRF4, lane);
        asm volatile("cp.async.commit_group;" ::: "memory");   // empty group ok near tail

        // Fold slog, butterfly over the 16-lane group.
        #pragma unroll
        for (int s = 0; s < 3; ++s)
            #pragma unroll
            for (int t = 0; t < 3; ++t)
                acc[s][t] += slog[s];
        #pragma unroll
        for (int off = 8; off > 0; off >>= 1)
            #pragma unroll
            for (int s = 0; s < 3; ++s) {
                acc[s][0] += __shfl_xor_sync(0xffffffffu, acc[s][0], off);
                acc[s][1] += __shfl_xor_sync(0xffffffffu, acc[s][1], off);
                acc[s][2] += __shfl_xor_sync(0xffffffffu, acc[s][2], off);
            }

        if (r == 0) {                         // lanes 0 and 16: one batch each
            float C[3][3];
            #pragma unroll
            for (int s = 0; s < 3; ++s)
                #pragma unroll
                for (int t = 0; t < 3; ++t)
                    C[s][t] = -LN2 * acc[s][t];

            // 6 permutations (itertools order); strict < keeps first-min (argmin).
            float best = C[0][0] + C[1][1] + C[2][2];
            int b0 = 0, b1 = 1, b2 = 2;
            float L;
            L = C[0][0] + C[2][1] + C[1][2]; if (L < best) { best = L; b0 = 0; b1 = 2; b2 = 1; }
            L = C[1][0] + C[0][1] + C[2][2]; if (L < best) { best = L; b0 = 1; b1 = 0; b2 = 2; }
            L = C[1][0] + C[2][1] + C[0][2]; if (L < best) { best = L; b0 = 1; b1 = 2; b2 = 0; }
            L = C[2][0] + C[0][1] + C[1][2]; if (L < best) { best = L; b0 = 2; b1 = 0; b2 = 1; }
            L = C[2][0] + C[1][1] + C[0][2]; if (L < best) { best = L; b0 = 2; b1 = 1; b2 = 0; }

            float q0c = (b0 == 0) ? c0 : ((b0 == 1) ? c1 : c2);
            float q1c = (b1 == 0) ? c0 : ((b1 == 1) ? c1 : c2);
            float q2c = (b2 == 0) ? c0 : ((b2 == 1) ? c1 : c2);
            float catsum = bce1(q0c, l0) + bce1(q1c, l1) + bce1(q2c, l2);

            vsum += best * (1.0f / 300.0f) * (1.0f / (float)NB)
                  + catsum * (1.0f / (3.0f * (float)NB));
        }
    }

    // ---- deterministic block reduction ----
    __shared__ float sm[TPB];
    sm[tid] = vsum;
    __syncthreads();
    #pragma unroll
    for (int off = TPB / 2; off > 0; off >>= 1) {
        if (tid < off) sm[tid] += sm[tid + off];
        __syncthreads();
    }

    __shared__ unsigned sticket;
    if (tid == 0) {
        g_partials[blockIdx.x] = sm[0];
        __threadfence();
        sticket = atomicAdd(&g_counter, 1u);
    }
    __syncthreads();

    // Last block sums all 1024 partials in fixed order (deterministic), resets counter.
    if (sticket == NBLK - 1) {
        __threadfence();
        float v = 0.f;
        #pragma unroll
        for (int i = 0; i < NBLK / TPB; ++i)     // 8 per thread, fixed order
            v += g_partials[tid + i * TPB];
        sm[tid] = v;
        __syncthreads();
        #pragma unroll
        for (int off = TPB / 2; off > 0; off >>= 1) {
            if (tid < off) sm[tid] += sm[tid + off];
            __syncthreads();
        }
        if (tid == 0) {
            out[0] = sm[0];
            g_counter = 0;                        // self-reset for graph replays
        }
    }
}

extern "C" void kernel_launch(void* const* d_in, const int* in_sizes, int n_in,
                              void* d_out, int out_size)
{
    const float* A    = (const float*)d_in[0]; // assignments        (B,3,10,10)
    const float* CAT  = (const float*)d_in[1]; // category           (B,3)
    const float* Y    = (const float*)d_in[2]; // assignments_labels (B,3,10,10)
    const float* CATL = (const float*)d_in[3]; // category_labels    (B,3)

    cudaFuncSetAttribute(loss_kernel, cudaFuncAttributeMaxDynamicSharedMemorySize, SMEM_BYTES);
    loss_kernel<<<NBLK, TPB, SMEM_BYTES>>>(A, CAT, Y, CATL, (float*)d_out);
}

// round 16
// speedup vs baseline: 1.0556x; 1.0556x over previous
#include <cuda_runtime.h>
#include <cuda_bf16.h>

#define NB     65536
#define TPB    128                    // 4 warps
#define WPB    4
#define NQ     2                      // quads per warp (quad = 4 batches)
#define NBLK   (NB / (WPB * 4 * NQ))  // 2048 blocks
#define QBYTES     4800               // A quad slice: 300 float4
#define WARP_SMEM  (2 * QBYTES)       // double buffer (A only) = 9600
#define SMEM_BYTES (WPB * WARP_SMEM)  // 38400 -> 5 blocks/SM (20 warps)

#define LN2      0.69314718055994530942f
#define CLAMP_L2 (-144.26950408889634f)   // -100 / ln2

typedef unsigned long long ull;
#define F32X2_NEG1 0xBF800000BF800000ULL
#define F32X2_ONE  0x3F8000003F800000ULL

union F2U { float2 f; ull u; };

#define FMA2(d, a, b, c) asm("fma.rn.f32x2 %0, %1, %2, %3;" : "=l"(d) : "l"(a), "l"(b), "l"(c))
#define ADD2(d, a, b)    asm("add.rn.f32x2 %0, %1, %2;"     : "=l"(d) : "l"(a), "l"(b))

__device__ float        g_partials[NBLK];
__device__ unsigned int g_counter = 0;

__device__ __forceinline__ float clog2_(float x) {           // clip(log p,-100)/ln2
    return fmaxf(__log2f(x), CLAMP_L2);
}
__device__ __forceinline__ float bce1(float p, float y) {
    float lp = fmaxf(__logf(p), -100.0f);
    float lm = fmaxf(__logf(1.0f - p), -100.0f);
    return -(y * lp + (1.0f - y) * lm);
}

__device__ __forceinline__ void cp16(void* dst_smem, const void* src_gmem) {
    unsigned s = (unsigned)__cvta_generic_to_shared(dst_smem);
    asm volatile("cp.async.cg.shared.global [%0], [%1], 16;" :: "r"(s), "l"(src_gmem) : "memory");
}

// Warp-scope stage of one A-quad: 300 contiguous float4.
__device__ __forceinline__ void stage_quadA(char* dst, const float4* gA, int lane)
{
    #pragma unroll
    for (int i = 0; i < 10; ++i) {
        int idx = i * 32 + lane;
        if (idx < 300)
            cp16(dst + idx * 16, gA + idx);
    }
    asm volatile("cp.async.commit_group;" ::: "memory");
}

// One float4 chunk, packed-pair arithmetic (FFMA2). acc/slog in lg2 domain.
__device__ __forceinline__ void chunk_accum(const float4 av[3], const float4 yv[3],
                                            ull accp[3][3], ull slogp[3])
{
    ull yp[3][2];
    #pragma unroll
    for (int t = 0; t < 3; ++t) {
        F2U y0; y0.f = make_float2(yv[t].x, yv[t].y);
        F2U y1; y1.f = make_float2(yv[t].z, yv[t].w);
        yp[t][0] = y0.u; yp[t][1] = y1.u;
    }
    #pragma unroll
    for (int s = 0; s < 3; ++s) {
        F2U a0; a0.f = make_float2(av[s].x, av[s].y);
        F2U a1; a1.f = make_float2(av[s].z, av[s].w);
        ull om0, om1;                      // (1 - p) packed
        FMA2(om0, a0.u, F32X2_NEG1, F32X2_ONE);
        FMA2(om1, a1.u, F32X2_NEG1, F32X2_ONE);
        F2U o0; o0.u = om0;
        F2U o1; o1.u = om1;
        F2U lm0; lm0.f = make_float2(__log2f(o0.f.x), __log2f(o0.f.y));
        F2U lm1; lm1.f = make_float2(__log2f(o1.f.x), __log2f(o1.f.y));
        F2U lp0; lp0.f = make_float2(clog2_(av[s].x), clog2_(av[s].y));
        F2U lp1; lp1.f = make_float2(clog2_(av[s].z), clog2_(av[s].w));
        ull df0, df1;                      // lp - lm
        FMA2(df0, lm0.u, F32X2_NEG1, lp0.u);
        FMA2(df1, lm1.u, F32X2_NEG1, lp1.u);
        ADD2(slogp[s], slogp[s], lm0.u);
        ADD2(slogp[s], slogp[s], lm1.u);
        #pragma unroll
        for (int t = 0; t < 3; ++t) {
            FMA2(accp[s][t], yp[t][0], df0, accp[s][t]);
            FMA2(accp[s][t], yp[t][1], df1, accp[s][t]);
        }
    }
}

extern __shared__ char smem[];

__global__ void __launch_bounds__(TPB)
loss_kernel(const float* __restrict__ A, const float* __restrict__ CAT,
            const float* __restrict__ Y, const float* __restrict__ CATL,
            float* __restrict__ out)
{
    const int tid  = threadIdx.x;
    const int w    = tid >> 5;
    const int lane = tid & 31;
    const int g    = lane >> 3;          // batch within quad (0..3)
    const int r    = lane & 7;           // lane within 8-lane batch group

    char* buf[2] = { smem + w * WARP_SMEM, smem + w * WARP_SMEM + QBYTES };

    const size_t q0 = ((size_t)blockIdx.x * WPB + w) * NQ;   // first quad id
    const float4* gA = reinterpret_cast<const float4*>(A);

    // Prologue: stage A for quads q0, q0+1.
    stage_quadA(buf[0], gA + q0 * 300, lane);
    stage_quadA(buf[1], gA + (q0 + 1) * 300, lane);

    float vsum = 0.0f;

    #pragma unroll
    for (int q = 0; q < NQ; ++q) {
        const int b = (int)(q0 + q) * 4 + g;                 // this lane's batch
        const float4* y4 = reinterpret_cast<const float4*>(Y) + (size_t)b * 75 + r;

        // Issue Y loads for k=0 before waiting on A (independent of cp.async).
        float4 yv0[3];
        #pragma unroll
        for (int s = 0; s < 3; ++s) yv0[s] = y4[s * 25];

        // Epilogue operands prefetch (consumed late).
        float c0 = 0.5f, c1 = 0.5f, c2 = 0.5f, l0 = 0.5f, l1 = 0.5f, l2 = 0.5f;
        if (r == 0) {
            c0 = CAT[3 * b + 0];  c1 = CAT[3 * b + 1];  c2 = CAT[3 * b + 2];
            l0 = CATL[3 * b + 0]; l1 = CATL[3 * b + 1]; l2 = CATL[3 * b + 2];
        }

        asm volatile("cp.async.wait_group 1;" ::: "memory");
        __syncwarp();

        const char* aq = buf[q & 1] + g * 1200;              // rows at s*400

        ull accp[3][3] = {};
        ull slogp[3]   = {};

        #pragma unroll
        for (int k = 0; k < 3; ++k) {
            float4 av[3], yv[3];
            #pragma unroll
            for (int s = 0; s < 3; ++s)
                yv[s] = (k == 0) ? yv0[s] : y4[s * 25 + 8 * k];
            #pragma unroll
            for (int s = 0; s < 3; ++s)
                av[s] = *reinterpret_cast<const float4*>(aq + s * 400 + (r + 8 * k) * 16);
            chunk_accum(av, yv, accp, slogp);
        }

        float acc[3][3], slog[3];
        #pragma unroll
        for (int s = 0; s < 3; ++s) {
            F2U t0; t0.u = slogp[s];
            slog[s] = t0.f.x + t0.f.y;
            #pragma unroll
            for (int t = 0; t < 3; ++t) {
                F2U t1; t1.u = accp[s][t];
                acc[s][t] = t1.f.x + t1.f.y;
            }
        }

        // Ragged elements 96..99: lanes r<4 take one scalar each (A smem, Y gmem).
        {
            float ra[3], ry[3], dfr[3], lmr[3];
            #pragma unroll
            for (int s = 0; s < 3; ++s) {
                ra[s] = *reinterpret_cast<const float*>(aq + s * 400 + (96 + (r & 3)) * 4);
                ry[s] = (r < 4) ? Y[(size_t)b * 300 + s * 100 + 96 + r] : 0.5f;
                float lp = clog2_(ra[s]);
                lmr[s]   = __log2f(1.0f - ra[s]);
                dfr[s]   = lp - lmr[s];
            }
            if (r < 4) {
                #pragma unroll
                for (int s = 0; s < 3; ++s) {
                    slog[s] += lmr[s];
                    #pragma unroll
                    for (int t = 0; t < 3; ++t)
                        acc[s][t] = fmaf(ry[t], dfr[s], acc[s][t]);
                }
            }
        }

        // Done reading this A buffer; refill with quad q+2 (none for NQ=2 tail).
        __syncwarp();
        if (q + 2 < NQ)
            stage_quadA(buf[q & 1], gA + (q0 + q + 2) * 300, lane);

        // Fold slog, butterfly over the 8-lane group.
        #pragma unroll
        for (int s = 0; s < 3; ++s)
            #pragma unroll
            for (int t = 0; t < 3; ++t)
                acc[s][t] += slog[s];
        #pragma unroll
        for (int off = 4; off > 0; off >>= 1)
            #pragma unroll
            for (int s = 0; s < 3; ++s) {
                acc[s][0] += __shfl_xor_sync(0xffffffffu, acc[s][0], off);
                acc[s][1] += __shfl_xor_sync(0xffffffffu, acc[s][1], off);
                acc[s][2] += __shfl_xor_sync(0xffffffffu, acc[s][2], off);
            }

        if (r == 0) {
            float C[3][3];
            #pragma unroll
            for (int s = 0; s < 3; ++s)
                #pragma unroll
                for (int t = 0; t < 3; ++t)
                    C[s][t] = -LN2 * acc[s][t];

            // 6 permutations (itertools order); strict < keeps first-min (argmin).
            float best = C[0][0] + C[1][1] + C[2][2];
            int b0 = 0, b1 = 1, b2 = 2;
            float L;
            L = C[0][0] + C[2][1] + C[1][2]; if (L < best) { best = L; b0 = 0; b1 = 2; b2 = 1; }
            L = C[1][0] + C[0][1] + C[2][2]; if (L < best) { best = L; b0 = 1; b1 = 0; b2 = 2; }
            L = C[1][0] + C[2][1] + C[0][2]; if (L < best) { best = L; b0 = 1; b1 = 2; b2 = 0; }
            L = C[2][0] + C[0][1] + C[1][2]; if (L < best) { best = L; b0 = 2; b1 = 0; b2 = 1; }
            L = C[2][0] + C[1][1] + C[0][2]; if (L < best) { best = L; b0 = 2; b1 = 1; b2 = 0; }

            float q0c = (b0 == 0) ? c0 : ((b0 == 1) ? c1 : c2);
            float q1c = (b1 == 0) ? c0 : ((b1 == 1) ? c1 : c2);
            float q2c = (b2 == 0) ? c0 : ((b2 == 1) ? c1 : c2);
            float catsum = bce1(q0c, l0) + bce1(q1c, l1) + bce1(q2c, l2);

            vsum += best * (1.0f / 300.0f) * (1.0f / (float)NB)
                  + catsum * (1.0f / (3.0f * (float)NB));
        }
    }

    // ---- deterministic block reduction ----
    __shared__ float sm[TPB];
    sm[tid] = vsum;
    __syncthreads();
    #pragma unroll
    for (int off = TPB / 2; off > 0; off >>= 1) {
        if (tid < off) sm[tid] += sm[tid + off];
        __syncthreads();
    }

    __shared__ unsigned sticket;
    if (tid == 0) {
        g_partials[blockIdx.x] = sm[0];
        __threadfence();
        sticket = atomicAdd(&g_counter, 1u);
    }
    __syncthreads();

    // Last block sums all 2048 partials in fixed order (deterministic), resets counter.
    if (sticket == NBLK - 1) {
        __threadfence();
        float v = 0.f;
        #pragma unroll
        for (int i = 0; i < NBLK / TPB; ++i)     // 16 per thread, fixed order
            v += g_partials[tid + i * TPB];
        sm[tid] = v;
        __syncthreads();
        #pragma unroll
        for (int off = TPB / 2; off > 0; off >>= 1) {
            if (tid < off) sm[tid] += sm[tid + off];
            __syncthreads();
        }
        if (tid == 0) {
            out[0] = sm[0];
            g_counter = 0;                        // self-reset for graph replays
        }
    }
}

extern "C" void kernel_launch(void* const* d_in, const int* in_sizes, int n_in,
                              void* d_out, int out_size)
{
    const float* A    = (const float*)d_in[0]; // assignments        (B,3,10,10)
    const float* CAT  = (const float*)d_in[1]; // category           (B,3)
    const float* Y    = (const float*)d_in[2]; // assignments_labels (B,3,10,10)
    const float* CATL = (const float*)d_in[3]; // category_labels    (B,3)

    cudaFuncSetAttribute(loss_kernel, cudaFuncAttributeMaxDynamicSharedMemorySize, SMEM_BYTES);
    loss_kernel<<<NBLK, TPB, SMEM_BYTES>>>(A, CAT, Y, CATL, (float*)d_out);
}